// round 1
// baseline (speedup 1.0000x reference)
#include <cuda_runtime.h>
#include <math.h>

// q = prod_i cos(pi/2 + 2*x_i) = prod_i (-sin(2*x_i))
// out[row] = { scale*q, -scale*q }

__global__ __launch_bounds__(256) void qnn_kernel(
    const float* __restrict__ x,      // [B, 8]
    const float* __restrict__ scale,  // [1]
    float2* __restrict__ out,         // [B] of float2
    int B)
{
    int row = blockIdx.x * blockDim.x + threadIdx.x;
    if (row >= B) return;

    // 32-byte row, aligned: two float4 loads
    const float4* xr = reinterpret_cast<const float4*>(x + (size_t)row * 8);
    float4 a = xr[0];
    float4 b = xr[1];

    float q =
        (-sinf(2.0f * a.x)) * (-sinf(2.0f * a.y)) *
        (-sinf(2.0f * a.z)) * (-sinf(2.0f * a.w)) *
        (-sinf(2.0f * b.x)) * (-sinf(2.0f * b.y)) *
        (-sinf(2.0f * b.z)) * (-sinf(2.0f * b.w));

    float s = *scale;
    float v = s * q;
    out[row] = make_float2(v, -v);
}

extern "C" void kernel_launch(void* const* d_in, const int* in_sizes, int n_in,
                              void* d_out, int out_size)
{
    const float* x     = (const float*)d_in[0];  // [B, 8] float32
    // d_in[1] = weights (unused)
    const float* scale = (const float*)d_in[2];  // scalar float32

    int B = in_sizes[0] / 8;
    float2* out = (float2*)d_out;  // [B, 2] float32

    int threads = 256;
    int blocks = (B + threads - 1) / threads;
    qnn_kernel<<<blocks, threads>>>(x, scale, out, B);
}

// round 2
// speedup vs baseline: 1.2772x; 1.2772x over previous
#include <cuda_runtime.h>
#include <math.h>

// q = prod_i cos(pi/2 + 2*x_i) = prod_i (-sin(2*x_i)) = prod_i sin(2*x_i)  (8 factors, even)
// out[row] = { scale*q, -scale*q }

__global__ __launch_bounds__(256) void qnn_kernel(
    const float* __restrict__ x,      // [B, 8]
    const float* __restrict__ scale,  // [1]
    float2* __restrict__ out,         // [B] of float2
    int B)
{
    int row = blockIdx.x * blockDim.x + threadIdx.x;
    if (row >= B) return;

    const float4* xr = reinterpret_cast<const float4*>(x + (size_t)row * 8);
    float4 a = xr[0];
    float4 b = xr[1];

    float q = __sinf(2.0f * a.x) * __sinf(2.0f * a.y) *
              __sinf(2.0f * a.z) * __sinf(2.0f * a.w) *
              __sinf(2.0f * b.x) * __sinf(2.0f * b.y) *
              __sinf(2.0f * b.z) * __sinf(2.0f * b.w);

    float s = *scale;
    float v = s * q;
    out[row] = make_float2(v, -v);
}

extern "C" void kernel_launch(void* const* d_in, const int* in_sizes, int n_in,
                              void* d_out, int out_size)
{
    const float* x     = (const float*)d_in[0];  // [B, 8] float32
    // d_in[1] = weights (unused)
    const float* scale = (const float*)d_in[2];  // scalar float32

    int B = in_sizes[0] / 8;
    float2* out = (float2*)d_out;

    int threads = 256;
    int blocks = (B + threads - 1) / threads;
    qnn_kernel<<<blocks, threads>>>(x, scale, out, B);
}